// round 7
// baseline (speedup 1.0000x reference)
#include <cuda_runtime.h>
#include <math.h>

// ---------------------------------------------------------------------------
// Problem constants
// ---------------------------------------------------------------------------
#define BATCH      8
#define STRIDE_F   32.0f
#define N_CELLS    196         // 14*14
#define WS_GRID    14
#define NUM_CLS    20
#define HEAD_OUT   25          // 1 + 20 + 4
#define CONF_TH    0.01f
#define NMS_TH     0.5f

// ---------------------------------------------------------------------------
// Scratch (static __device__ arrays: allocation-free, capture-safe).
// Ping-pong aliasing, safe under sequential default-stream execution.
// ---------------------------------------------------------------------------
__device__ float g_bufA[8L * 64 * 224 * 224];    // 102.8 MB
__device__ float g_bufB[8L * 128 * 112 * 112];   //  51.4 MB
__device__ float g_pred [8 * HEAD_OUT * N_CELLS];
__device__ float g_boxes[8 * N_CELLS * 4];
__device__ float g_cls  [8 * N_CELLS * NUM_CLS];

// ---------------------------------------------------------------------------
// Packed fp32x2 helpers (sm_103a FFMA2 — ptxas never auto-fuses; PTX only).
// Per-lane .rn rounding == fmaf, so results are bit-identical to scalar.
// ---------------------------------------------------------------------------
__device__ __forceinline__ unsigned long long fma2(unsigned long long a,
                                                   unsigned long long b,
                                                   unsigned long long c)
{
    unsigned long long d;
    asm("fma.rn.f32x2 %0, %1, %2, %3;" : "=l"(d) : "l"(a), "l"(b), "l"(c));
    return d;
}
__device__ __forceinline__ unsigned long long bcast2(float v)
{
    unsigned long long d;
    asm("mov.b64 %0, {%1, %1};" : "=l"(d) : "f"(v));
    return d;
}
__device__ __forceinline__ void unpack2(unsigned long long p, float& lo, float& hi)
{
    asm("mov.b64 {%0, %1}, %2;" : "=f"(lo), "=f"(hi) : "l"(p));
}

// ---------------------------------------------------------------------------
// 3x3 stride-2 conv + ReLU, SAME padding (JAX: pad_lo=0, pad_hi=1).
//
// v3: FFMA2 rework.
//  - 128 threads, tile = 64 co x (8 rows x 16 cols); thread = 8 co x 8 rows.
//  - Accumulators packed over co-pairs: 32 x 64-bit regs.
//  - Weights staged co-contiguous ([cc][k][68]); one LDS.128 delivers two
//    (co,co+1) packed operands with zero pack MOVs.
//  - Inputs de-interleaved even/odd columns (stride-2 -> unit stride LDS,
//    16 distinct addrs/warp = broadcast); 8 LDS.32 + 8 mov.b64 bcasts/kpos.
//  - Inner loop: 50 issues per 64 MACs; all smem addrs [base + imm].
//  - Loader: warp = tile row, lane = column; pointer-increment addressing,
//    no div/mod.
// ---------------------------------------------------------------------------
template<int CIN, int COUT, int HIN, int WIN>
__global__ __launch_bounds__(128, 3)
void conv3x3s2_relu(const float* __restrict__ in,
                    const float* __restrict__ w,
                    float* __restrict__ out)
{
    constexpr int HOUT = HIN / 2;
    constexpr int WOUT = WIN / 2;
    constexpr int CHUNK = (CIN % 8 == 0) ? 8 : CIN;   // 8, or 3 for layer 1
    constexpr int NTX = (WOUT + 15) / 16;

    const int bx  = blockIdx.x % NTX;
    const int by  = blockIdx.x / NTX;
    const int ox0 = bx * 16;
    const int oy0 = by * 8;
    const int co0 = blockIdx.y * 64;
    const int b   = blockIdx.z;

    __shared__ float s_even[CHUNK][17][17];              // even input cols
    __shared__ float s_odd [CHUNK][17][16];              // odd  input cols
    __shared__ __align__(16) float s_w[CHUNK][9][68];    // [cc][k][co], pad 68

    const int tid  = threadIdx.x;   // 0..127
    const int tc   = tid >> 4;      // 0..7  -> co = co0 + tc*8 .. +7
    const int tp   = tid & 15;      // 0..15 -> output column within tile
    const int wrp  = tid >> 5;      // 0..3  (loader row group)
    const int lane = tid & 31;      // 0..31 (loader column)

    unsigned long long acc[4][8] = {};   // [co-pair][row]

    const float* in_b = in + (size_t)b * CIN * HIN * WIN;
    const float* wg   = w + (size_t)co0 * CIN * 9;

    for (int ci0 = 0; ci0 < CIN; ci0 += CHUNK) {
        __syncthreads();   // protect smem from previous iteration's readers

        // ---- input tile: CHUNK ch x 17 rows x 33 cols, structured loader ----
        {
            const float* gp = in_b + (size_t)ci0 * HIN * WIN;
#pragma unroll 1
            for (int cc = 0; cc < CHUNK; cc++) {
#pragma unroll
                for (int k = 0; k < 5; k++) {
                    const int ly = wrp + 4 * k;
                    if (ly < 17) {
                        const int iy = 2 * oy0 + ly;
                        const int ix = 2 * ox0 + lane;
                        float v = 0.0f;
                        if (iy < HIN && ix < WIN)
                            v = gp[(size_t)cc * HIN * WIN + (size_t)iy * WIN + ix];
                        if (lane & 1) s_odd [cc][ly][lane >> 1] = v;
                        else          s_even[cc][ly][lane >> 1] = v;
                        if (lane == 0) {            // 33rd column (lx = 32)
                            const int ix2 = 2 * ox0 + 32;
                            float v2 = 0.0f;
                            if (iy < HIN && ix2 < WIN)
                                v2 = gp[(size_t)cc * HIN * WIN + (size_t)iy * WIN + ix2];
                            s_even[cc][ly][16] = v2;
                        }
                    }
                }
            }
        }

        // ---- weights: coalesced read, transposed store [cc*9+k][co] ----
        {
            float* swf = &s_w[0][0][0];
            for (int idx = tid; idx < 64 * CHUNK * 9; idx += 128) {
                int co  = idx / (CHUNK * 9);
                int rem = idx - co * (CHUNK * 9);   // rem = cc*9 + k
                swf[rem * 68 + co] = wg[(size_t)co * CIN * 9 + ci0 * 9 + rem];
            }
        }
        __syncthreads();

        // ---- compute: packed co-pair FFMA2 ----
        const float* pe = &s_even[0][0][0] + tp;
        const float* po = &s_odd [0][0][0] + tp;
        const float* pw = &s_w[0][0][0] + tc * 8;

#pragma unroll 1
        for (int cc = 0; cc < CHUNK; cc++) {
#pragma unroll
            for (int ky = 0; ky < 3; ky++) {
#pragma unroll
                for (int kx = 0; kx < 3; kx++) {
                    const int kp = ky * 3 + kx;
                    // two LDS.128 -> four packed (co,co+1) weight pairs
                    ulonglong2 wA = *reinterpret_cast<const ulonglong2*>(pw + kp * 68);
                    ulonglong2 wB = *reinterpret_cast<const ulonglong2*>(pw + kp * 68 + 4);
                    unsigned long long iv2[8];
#pragma unroll
                    for (int r = 0; r < 8; r++) {
                        const int ly = 2 * r + ky;
                        const float v = (kx == 1) ? po[ly * 16]
                                                  : pe[ly * 17 + (kx >> 1)];
                        iv2[r] = bcast2(v);
                    }
#pragma unroll
                    for (int r = 0; r < 8; r++) {
                        acc[0][r] = fma2(wA.x, iv2[r], acc[0][r]);
                        acc[1][r] = fma2(wA.y, iv2[r], acc[1][r]);
                        acc[2][r] = fma2(wB.x, iv2[r], acc[2][r]);
                        acc[3][r] = fma2(wB.y, iv2[r], acc[3][r]);
                    }
                }
            }
            pe += 17 * 17;   // 289
            po += 17 * 16;   // 272
            pw += 9 * 68;    // 612
        }
    }

    // ---- epilogue: unpack, ReLU, store ----
    float* out_b = out + (size_t)b * COUT * HOUT * WOUT;
    const int ox = ox0 + tp;
    if (ox < WOUT) {
#pragma unroll
        for (int j2 = 0; j2 < 4; j2++) {
            const int co = co0 + tc * 8 + 2 * j2;
#pragma unroll
            for (int r = 0; r < 8; r++) {
                const int oy = oy0 + r;
                if (oy < HOUT) {
                    float lo, hi;
                    unpack2(acc[j2][r], lo, hi);
                    out_b[((size_t)co * HOUT + oy) * WOUT + ox]       = fmaxf(lo, 0.0f);
                    out_b[((size_t)(co + 1) * HOUT + oy) * WOUT + ox] = fmaxf(hi, 0.0f);
                }
            }
        }
    }
}

// ---------------------------------------------------------------------------
// 1x1 head conv: pred[b][o][p] = sum_ci h5[b][ci][p] * w[o][ci]
// ---------------------------------------------------------------------------
__global__ void yolo_head_kernel(const float* __restrict__ h5,
                                 const float* __restrict__ w,
                                 float* __restrict__ pred)
{
    const int b = blockIdx.x;
    const int o = blockIdx.y;
    const int p = threadIdx.x;
    if (p >= N_CELLS) return;
    const float* hb = h5 + (size_t)b * 512 * N_CELLS;
    const float* wo = w + o * 512;
    float s = 0.0f;
#pragma unroll 8
    for (int ci = 0; ci < 512; ci++)
        s = fmaf(hb[ci * N_CELLS + p], wo[ci], s);
    pred[(b * HEAD_OUT + o) * N_CELLS + p] = s;
}

// ---------------------------------------------------------------------------
// Decode: sigmoid conf, softmax*conf class scores, box decode + clip.
// ---------------------------------------------------------------------------
__global__ void yolo_decode_kernel(const float* __restrict__ pred,
                                   float* __restrict__ boxes,
                                   float* __restrict__ cls,
                                   float* __restrict__ out)
{
    const int b = blockIdx.x;
    const int p = threadIdx.x;
    if (p >= N_CELLS) return;
    const float* pb = pred + (size_t)b * HEAD_OUT * N_CELLS;

    float conf = 1.0f / (1.0f + expf(-pb[p]));

    float v[NUM_CLS];
    float m = -1e30f;
#pragma unroll
    for (int c = 0; c < NUM_CLS; c++) {
        v[c] = pb[(1 + c) * N_CELLS + p];
        m = fmaxf(m, v[c]);
    }
    float s = 0.0f;
#pragma unroll
    for (int c = 0; c < NUM_CLS; c++) { v[c] = expf(v[c] - m); s += v[c]; }
    float inv = conf / s;

    float tx = pb[21 * N_CELLS + p];
    float ty = pb[22 * N_CELLS + p];
    float tw = pb[23 * N_CELLS + p];
    float th = pb[24 * N_CELLS + p];

    float gx = (float)(p % WS_GRID);
    float gy = (float)(p / WS_GRID);
    float cx = (1.0f / (1.0f + expf(-tx)) + gx) * STRIDE_F;
    float cy = (1.0f / (1.0f + expf(-ty)) + gy) * STRIDE_F;
    float bw = expf(tw) * STRIDE_F;
    float bh = expf(th) * STRIDE_F;

    float x1 = (cx - bw * 0.5f) / 448.0f;
    float y1 = (cy - bh * 0.5f) / 448.0f;
    float x2 = (cx + bw * 0.5f) / 448.0f;
    float y2 = (cy + bh * 0.5f) / 448.0f;
    x1 = fminf(fmaxf(x1, 0.0f), 1.0f);
    y1 = fminf(fmaxf(y1, 0.0f), 1.0f);
    x2 = fminf(fmaxf(x2, 0.0f), 1.0f);
    y2 = fminf(fmaxf(y2, 0.0f), 1.0f);

    const int row = b * N_CELLS + p;
    boxes[row * 4 + 0] = x1;
    boxes[row * 4 + 1] = y1;
    boxes[row * 4 + 2] = x2;
    boxes[row * 4 + 3] = y2;
    out[row * 24 + 0] = x1;
    out[row * 24 + 1] = y1;
    out[row * 24 + 2] = x2;
    out[row * 24 + 3] = y2;
#pragma unroll
    for (int c = 0; c < NUM_CLS; c++)
        cls[row * NUM_CLS + c] = v[c] * inv;
}

// ---------------------------------------------------------------------------
// Per-(batch, class) greedy NMS. One block per problem.
// ---------------------------------------------------------------------------
__global__ void yolo_nms_kernel(const float* __restrict__ boxes,
                                const float* __restrict__ cls,
                                float* __restrict__ out)
{
    const int c = blockIdx.x;   // class
    const int b = blockIdx.y;   // batch
    const int t = threadIdx.x;

    __shared__ float ss[N_CELLS];
    __shared__ float sx1[N_CELLS], sy1[N_CELLS], sx2[N_CELLS], sy2[N_CELLS];
    __shared__ float sa[N_CELLS];
    __shared__ int   sorder[N_CELLS];
    __shared__ int   skeep[N_CELLS];

    if (t < N_CELLS) {
        const int row = b * N_CELLS + t;
        ss[t] = cls[row * NUM_CLS + c];
        float x1 = boxes[row * 4 + 0];
        float y1 = boxes[row * 4 + 1];
        float x2 = boxes[row * 4 + 2];
        float y2 = boxes[row * 4 + 3];
        sx1[t] = x1; sy1[t] = y1; sx2[t] = x2; sy2[t] = y2;
        sa[t] = fmaxf(x2 - x1, 0.0f) * fmaxf(y2 - y1, 0.0f);
    }
    __syncthreads();

    if (t < N_CELLS) {   // stable descending rank (== stable argsort of -s)
        float sp = ss[t];
        int r = 0;
        for (int q = 0; q < N_CELLS; q++) {
            float sq = ss[q];
            r += (sq > sp) || (sq == sp && q < t);
        }
        sorder[r] = t;
        skeep[r]  = (sp > CONF_TH) ? 1 : 0;
    }
    __syncthreads();

    int pj = 0;
    float bx1 = 0.f, by1 = 0.f, bx2 = 0.f, by2 = 0.f, ba = 0.f;
    if (t < N_CELLS) {
        pj  = sorder[t];
        bx1 = sx1[pj]; by1 = sy1[pj]; bx2 = sx2[pj]; by2 = sy2[pj]; ba = sa[pj];
    }

    for (int i = 0; i < N_CELLS - 1; i++) {
        if (skeep[i]) {
            int pi = sorder[i];
            float ax1 = sx1[pi], ay1 = sy1[pi];
            float ax2 = sx2[pi], ay2 = sy2[pi];
            float aa  = sa[pi];
            if (t < N_CELLS && t > i && skeep[t]) {
                float ix1 = fmaxf(ax1, bx1), iy1 = fmaxf(ay1, by1);
                float ix2 = fminf(ax2, bx2), iy2 = fminf(ay2, by2);
                float inter = fmaxf(ix2 - ix1, 0.0f) * fmaxf(iy2 - iy1, 0.0f);
                float iou = inter / (aa + ba - inter + 1e-14f);
                if (iou > NMS_TH) skeep[t] = 0;
            }
        }
        __syncthreads();
    }

    if (t < N_CELLS) {
        const int row = b * N_CELLS + pj;
        out[row * 24 + 4 + c] = ss[pj] * (skeep[t] ? 1.0f : 0.0f);
    }
}

// ---------------------------------------------------------------------------
// Launch
// ---------------------------------------------------------------------------
extern "C" void kernel_launch(void* const* d_in, const int* in_sizes, int n_in,
                              void* d_out, int out_size)
{
    const float* x  = (const float*)d_in[0];
    const float* w1 = (const float*)d_in[1];
    const float* w2 = (const float*)d_in[2];
    const float* w3 = (const float*)d_in[3];
    const float* w4 = (const float*)d_in[4];
    const float* w5 = (const float*)d_in[5];
    const float* wh = (const float*)d_in[6];
    float* out = (float*)d_out;

    float *bufA, *bufB, *pred, *boxes, *cls;
    cudaGetSymbolAddress((void**)&bufA, g_bufA);
    cudaGetSymbolAddress((void**)&bufB, g_bufB);
    cudaGetSymbolAddress((void**)&pred, g_pred);
    cudaGetSymbolAddress((void**)&boxes, g_boxes);
    cudaGetSymbolAddress((void**)&cls, g_cls);

    float* h1 = bufA;
    float* h2 = bufB;
    float* h3 = bufA;
    float* h4 = bufB;
    float* h5 = bufA;

    {   // L1: 3 -> 64, 448 -> 224
        constexpr int NTX = (224 + 15) / 16, NTY = (224 + 7) / 8;
        conv3x3s2_relu<3, 64, 448, 448><<<dim3(NTX * NTY, 1, BATCH), 128>>>(x, w1, h1);
    }
    {   // L2: 64 -> 128, 224 -> 112
        constexpr int NTX = (112 + 15) / 16, NTY = (112 + 7) / 8;
        conv3x3s2_relu<64, 128, 224, 224><<<dim3(NTX * NTY, 2, BATCH), 128>>>(h1, w2, h2);
    }
    {   // L3: 128 -> 256, 112 -> 56
        constexpr int NTX = (56 + 15) / 16, NTY = (56 + 7) / 8;
        conv3x3s2_relu<128, 256, 112, 112><<<dim3(NTX * NTY, 4, BATCH), 128>>>(h2, w3, h3);
    }
    {   // L4: 256 -> 512, 56 -> 28
        constexpr int NTX = (28 + 15) / 16, NTY = (28 + 7) / 8;
        conv3x3s2_relu<256, 512, 56, 56><<<dim3(NTX * NTY, 8, BATCH), 128>>>(h3, w4, h4);
    }
    {   // L5: 512 -> 512, 28 -> 14
        constexpr int NTX = (14 + 15) / 16, NTY = (14 + 7) / 8;
        conv3x3s2_relu<512, 512, 28, 28><<<dim3(NTX * NTY, 8, BATCH), 128>>>(h4, w5, h5);
    }

    yolo_head_kernel<<<dim3(BATCH, HEAD_OUT), 224>>>(h5, wh, pred);
    yolo_decode_kernel<<<BATCH, 224>>>(pred, boxes, cls, out);
    yolo_nms_kernel<<<dim3(NUM_CLS, BATCH), 224>>>(boxes, cls, out);
}

// round 8
// speedup vs baseline: 1.6726x; 1.6726x over previous
#include <cuda_runtime.h>
#include <math.h>

// ---------------------------------------------------------------------------
// Problem constants
// ---------------------------------------------------------------------------
#define BATCH      8
#define STRIDE_F   32.0f
#define N_CELLS    196         // 14*14
#define WS_GRID    14
#define NUM_CLS    20
#define HEAD_OUT   25          // 1 + 20 + 4
#define CONF_TH    0.01f
#define NMS_TH     0.5f

// ---------------------------------------------------------------------------
// Scratch (static __device__ arrays: allocation-free, capture-safe).
// Ping-pong aliasing, safe under sequential default-stream execution.
// ---------------------------------------------------------------------------
__device__ float g_bufA[8L * 64 * 224 * 224];    // 102.8 MB
__device__ float g_bufB[8L * 128 * 112 * 112];   //  51.4 MB
__device__ float g_pred [8 * HEAD_OUT * N_CELLS];
__device__ float g_boxes[8 * N_CELLS * 4];
__device__ float g_cls  [8 * N_CELLS * NUM_CLS];

// ---------------------------------------------------------------------------
// 3x3 stride-2 conv + ReLU, SAME padding (JAX: pad_lo=0, pad_hi=1).
//
// v4: scalar FMA, occupancy + issue-economy rework.
//  - 128 threads/block, tile = 64 co x (4 rows x 16 cols).
//  - Thread = 8 co x 4 rows = 32 fp32 accumulators (regs ~70 -> 6 CTAs/SM,
//    24 warps/SM vs 16 before).
//  - No intermediate wv[]/iv[] arrays: float4 weight components and scalar
//    iv loads feed FMAs directly (the arrays were ~16 ALU MOVs per k-pos,
//    measured as alu=27.3% in the R6 profile).
//  - Weights staged co-contiguous ([cc][k][68]) -> 2x LDS.128 per k-pos.
//  - Inputs de-interleaved even/odd columns: stride-2 access -> unit-stride,
//    16 distinct addrs/warp = conflict-free broadcast.
//  - All inner-loop smem addresses are [base + immediate]; 3 pointer bumps
//    per input channel.
// ---------------------------------------------------------------------------
template<int CIN, int COUT, int HIN, int WIN>
__global__ __launch_bounds__(128, 6)
void conv3x3s2_relu(const float* __restrict__ in,
                    const float* __restrict__ w,
                    float* __restrict__ out)
{
    constexpr int HOUT = HIN / 2;
    constexpr int WOUT = WIN / 2;
    constexpr int CHUNK = (CIN % 8 == 0) ? 8 : CIN;   // 8, or 3 for layer 1
    constexpr int NTX = (WOUT + 15) / 16;
    constexpr int TIN = CHUNK * 9 * 33;               // input tile elements

    const int bx  = blockIdx.x % NTX;
    const int by  = blockIdx.x / NTX;
    const int ox0 = bx * 16;
    const int oy0 = by * 4;
    const int co0 = blockIdx.y * 64;
    const int b   = blockIdx.z;

    __shared__ float s_even[CHUNK][9][17];               // even input cols
    __shared__ float s_odd [CHUNK][9][16];               // odd  input cols
    __shared__ __align__(16) float s_w[CHUNK][9][68];    // [cc][k][co], pad 68

    const int tid = threadIdx.x;   // 0..127
    const int tc  = tid >> 4;      // 0..7  -> co = co0 + tc*8 .. +7
    const int tp  = tid & 15;      // 0..15 -> output column within tile

    float acc[8][4] = {};          // [co][row], constant-indexed after unroll

    const float* in_b = in + (size_t)b * CIN * HIN * WIN;
    const float* wg   = w + (size_t)co0 * CIN * 9;

    for (int ci0 = 0; ci0 < CIN; ci0 += CHUNK) {
        __syncthreads();   // protect smem from previous iteration's readers

        // ---- input tile: CHUNK channels x 9 rows x 33 cols ----
        for (int idx = tid; idx < TIN; idx += 128) {
            int cc  = idx / (9 * 33);
            int rem = idx - cc * (9 * 33);
            int ly  = rem / 33;
            int lx  = rem - ly * 33;
            int iy  = 2 * oy0 + ly;        // pad_lo = 0: never negative
            int ix  = 2 * ox0 + lx;
            float v = 0.0f;
            if (iy < HIN && ix < WIN)
                v = in_b[((size_t)(ci0 + cc) * HIN + iy) * WIN + ix];
            if (lx & 1) s_odd [cc][ly][lx >> 1] = v;
            else        s_even[cc][ly][lx >> 1] = v;
        }

        // ---- weights: coalesced read, transposed store [cc*9+k][co] ----
        {
            float* swf = &s_w[0][0][0];
            for (int idx = tid; idx < 64 * CHUNK * 9; idx += 128) {
                int co  = idx / (CHUNK * 9);
                int rem = idx - co * (CHUNK * 9);   // rem = cc*9 + k
                swf[rem * 68 + co] = wg[(size_t)co * CIN * 9 + ci0 * 9 + rem];
            }
        }
        __syncthreads();

        // ---- compute: direct float4/scalar feeds, no staging arrays ----
        const float* pe = &s_even[0][0][0] + tp;
        const float* po = &s_odd [0][0][0] + tp;
        const float* pw = &s_w[0][0][0] + tc * 8;

#pragma unroll 1
        for (int cc = 0; cc < CHUNK; cc++) {
#pragma unroll
            for (int ky = 0; ky < 3; ky++) {
#pragma unroll
                for (int kx = 0; kx < 3; kx++) {
                    const int kp = ky * 3 + kx;
                    const float4 wa = *reinterpret_cast<const float4*>(pw + kp * 68);
                    const float4 wb = *reinterpret_cast<const float4*>(pw + kp * 68 + 4);
#pragma unroll
                    for (int r = 0; r < 4; r++) {
                        const int ly = 2 * r + ky;
                        const float iv = (kx == 1) ? po[ly * 16]
                                                   : pe[ly * 17 + (kx >> 1)];
                        acc[0][r] = fmaf(wa.x, iv, acc[0][r]);
                        acc[1][r] = fmaf(wa.y, iv, acc[1][r]);
                        acc[2][r] = fmaf(wa.z, iv, acc[2][r]);
                        acc[3][r] = fmaf(wa.w, iv, acc[3][r]);
                        acc[4][r] = fmaf(wb.x, iv, acc[4][r]);
                        acc[5][r] = fmaf(wb.y, iv, acc[5][r]);
                        acc[6][r] = fmaf(wb.z, iv, acc[6][r]);
                        acc[7][r] = fmaf(wb.w, iv, acc[7][r]);
                    }
                }
            }
            pe += 9 * 17;   // 153
            po += 9 * 16;   // 144
            pw += 9 * 68;   // 612
        }
    }

    // ---- epilogue: ReLU + store ----
    float* out_b = out + (size_t)b * COUT * HOUT * WOUT;
    const int ox = ox0 + tp;
    if (ox < WOUT) {
#pragma unroll
        for (int j = 0; j < 8; j++) {
            const int co = co0 + tc * 8 + j;
#pragma unroll
            for (int r = 0; r < 4; r++) {
                const int oy = oy0 + r;
                if (oy < HOUT)
                    out_b[((size_t)co * HOUT + oy) * WOUT + ox] = fmaxf(acc[j][r], 0.0f);
            }
        }
    }
}

// ---------------------------------------------------------------------------
// 1x1 head conv: pred[b][o][p] = sum_ci h5[b][ci][p] * w[o][ci]
// ---------------------------------------------------------------------------
__global__ void yolo_head_kernel(const float* __restrict__ h5,
                                 const float* __restrict__ w,
                                 float* __restrict__ pred)
{
    const int b = blockIdx.x;
    const int o = blockIdx.y;
    const int p = threadIdx.x;
    if (p >= N_CELLS) return;
    const float* hb = h5 + (size_t)b * 512 * N_CELLS;
    const float* wo = w + o * 512;
    float s = 0.0f;
#pragma unroll 8
    for (int ci = 0; ci < 512; ci++)
        s = fmaf(hb[ci * N_CELLS + p], wo[ci], s);
    pred[(b * HEAD_OUT + o) * N_CELLS + p] = s;
}

// ---------------------------------------------------------------------------
// Decode: sigmoid conf, softmax*conf class scores, box decode + clip.
// ---------------------------------------------------------------------------
__global__ void yolo_decode_kernel(const float* __restrict__ pred,
                                   float* __restrict__ boxes,
                                   float* __restrict__ cls,
                                   float* __restrict__ out)
{
    const int b = blockIdx.x;
    const int p = threadIdx.x;
    if (p >= N_CELLS) return;
    const float* pb = pred + (size_t)b * HEAD_OUT * N_CELLS;

    float conf = 1.0f / (1.0f + expf(-pb[p]));

    float v[NUM_CLS];
    float m = -1e30f;
#pragma unroll
    for (int c = 0; c < NUM_CLS; c++) {
        v[c] = pb[(1 + c) * N_CELLS + p];
        m = fmaxf(m, v[c]);
    }
    float s = 0.0f;
#pragma unroll
    for (int c = 0; c < NUM_CLS; c++) { v[c] = expf(v[c] - m); s += v[c]; }
    float inv = conf / s;

    float tx = pb[21 * N_CELLS + p];
    float ty = pb[22 * N_CELLS + p];
    float tw = pb[23 * N_CELLS + p];
    float th = pb[24 * N_CELLS + p];

    float gx = (float)(p % WS_GRID);
    float gy = (float)(p / WS_GRID);
    float cx = (1.0f / (1.0f + expf(-tx)) + gx) * STRIDE_F;
    float cy = (1.0f / (1.0f + expf(-ty)) + gy) * STRIDE_F;
    float bw = expf(tw) * STRIDE_F;
    float bh = expf(th) * STRIDE_F;

    float x1 = (cx - bw * 0.5f) / 448.0f;
    float y1 = (cy - bh * 0.5f) / 448.0f;
    float x2 = (cx + bw * 0.5f) / 448.0f;
    float y2 = (cy + bh * 0.5f) / 448.0f;
    x1 = fminf(fmaxf(x1, 0.0f), 1.0f);
    y1 = fminf(fmaxf(y1, 0.0f), 1.0f);
    x2 = fminf(fmaxf(x2, 0.0f), 1.0f);
    y2 = fminf(fmaxf(y2, 0.0f), 1.0f);

    const int row = b * N_CELLS + p;
    boxes[row * 4 + 0] = x1;
    boxes[row * 4 + 1] = y1;
    boxes[row * 4 + 2] = x2;
    boxes[row * 4 + 3] = y2;
    out[row * 24 + 0] = x1;
    out[row * 24 + 1] = y1;
    out[row * 24 + 2] = x2;
    out[row * 24 + 3] = y2;
#pragma unroll
    for (int c = 0; c < NUM_CLS; c++)
        cls[row * NUM_CLS + c] = v[c] * inv;
}

// ---------------------------------------------------------------------------
// Per-(batch, class) greedy NMS. One block per problem.
// Stable descending rank (== stable argsort of -scores), then 196
// barrier-stepped suppression iterations (only kept boxes suppress).
// ---------------------------------------------------------------------------
__global__ void yolo_nms_kernel(const float* __restrict__ boxes,
                                const float* __restrict__ cls,
                                float* __restrict__ out)
{
    const int c = blockIdx.x;   // class
    const int b = blockIdx.y;   // batch
    const int t = threadIdx.x;

    __shared__ float ss[N_CELLS];
    __shared__ float sx1[N_CELLS], sy1[N_CELLS], sx2[N_CELLS], sy2[N_CELLS];
    __shared__ float sa[N_CELLS];
    __shared__ int   sorder[N_CELLS];
    __shared__ int   skeep[N_CELLS];

    if (t < N_CELLS) {
        const int row = b * N_CELLS + t;
        ss[t] = cls[row * NUM_CLS + c];
        float x1 = boxes[row * 4 + 0];
        float y1 = boxes[row * 4 + 1];
        float x2 = boxes[row * 4 + 2];
        float y2 = boxes[row * 4 + 3];
        sx1[t] = x1; sy1[t] = y1; sx2[t] = x2; sy2[t] = y2;
        sa[t] = fmaxf(x2 - x1, 0.0f) * fmaxf(y2 - y1, 0.0f);
    }
    __syncthreads();

    if (t < N_CELLS) {
        float sp = ss[t];
        int r = 0;
        for (int q = 0; q < N_CELLS; q++) {
            float sq = ss[q];
            r += (sq > sp) || (sq == sp && q < t);
        }
        sorder[r] = t;
        skeep[r]  = (sp > CONF_TH) ? 1 : 0;
    }
    __syncthreads();

    int pj = 0;
    float bx1 = 0.f, by1 = 0.f, bx2 = 0.f, by2 = 0.f, ba = 0.f;
    if (t < N_CELLS) {
        pj  = sorder[t];
        bx1 = sx1[pj]; by1 = sy1[pj]; bx2 = sx2[pj]; by2 = sy2[pj]; ba = sa[pj];
    }

    for (int i = 0; i < N_CELLS - 1; i++) {
        if (skeep[i]) {
            int pi = sorder[i];
            float ax1 = sx1[pi], ay1 = sy1[pi];
            float ax2 = sx2[pi], ay2 = sy2[pi];
            float aa  = sa[pi];
            if (t < N_CELLS && t > i && skeep[t]) {
                float ix1 = fmaxf(ax1, bx1), iy1 = fmaxf(ay1, by1);
                float ix2 = fminf(ax2, bx2), iy2 = fminf(ay2, by2);
                float inter = fmaxf(ix2 - ix1, 0.0f) * fmaxf(iy2 - iy1, 0.0f);
                float iou = inter / (aa + ba - inter + 1e-14f);
                if (iou > NMS_TH) skeep[t] = 0;
            }
        }
        __syncthreads();
    }

    if (t < N_CELLS) {
        const int row = b * N_CELLS + pj;
        out[row * 24 + 4 + c] = ss[pj] * (skeep[t] ? 1.0f : 0.0f);
    }
}

// ---------------------------------------------------------------------------
// Launch
// ---------------------------------------------------------------------------
extern "C" void kernel_launch(void* const* d_in, const int* in_sizes, int n_in,
                              void* d_out, int out_size)
{
    const float* x  = (const float*)d_in[0];
    const float* w1 = (const float*)d_in[1];
    const float* w2 = (const float*)d_in[2];
    const float* w3 = (const float*)d_in[3];
    const float* w4 = (const float*)d_in[4];
    const float* w5 = (const float*)d_in[5];
    const float* wh = (const float*)d_in[6];
    float* out = (float*)d_out;

    float *bufA, *bufB, *pred, *boxes, *cls;
    cudaGetSymbolAddress((void**)&bufA, g_bufA);
    cudaGetSymbolAddress((void**)&bufB, g_bufB);
    cudaGetSymbolAddress((void**)&pred, g_pred);
    cudaGetSymbolAddress((void**)&boxes, g_boxes);
    cudaGetSymbolAddress((void**)&cls, g_cls);

    float* h1 = bufA;
    float* h2 = bufB;
    float* h3 = bufA;
    float* h4 = bufB;
    float* h5 = bufA;

    {   // L1: 3 -> 64, 448 -> 224
        constexpr int NTX = (224 + 15) / 16, NTY = (224 + 3) / 4;
        conv3x3s2_relu<3, 64, 448, 448><<<dim3(NTX * NTY, 1, BATCH), 128>>>(x, w1, h1);
    }
    {   // L2: 64 -> 128, 224 -> 112
        constexpr int NTX = (112 + 15) / 16, NTY = (112 + 3) / 4;
        conv3x3s2_relu<64, 128, 224, 224><<<dim3(NTX * NTY, 2, BATCH), 128>>>(h1, w2, h2);
    }
    {   // L3: 128 -> 256, 112 -> 56
        constexpr int NTX = (56 + 15) / 16, NTY = (56 + 3) / 4;
        conv3x3s2_relu<128, 256, 112, 112><<<dim3(NTX * NTY, 4, BATCH), 128>>>(h2, w3, h3);
    }
    {   // L4: 256 -> 512, 56 -> 28
        constexpr int NTX = (28 + 15) / 16, NTY = (28 + 3) / 4;
        conv3x3s2_relu<256, 512, 56, 56><<<dim3(NTX * NTY, 8, BATCH), 128>>>(h3, w4, h4);
    }
    {   // L5: 512 -> 512, 28 -> 14
        constexpr int NTX = (14 + 15) / 16, NTY = (14 + 3) / 4;
        conv3x3s2_relu<512, 512, 28, 28><<<dim3(NTX * NTY, 8, BATCH), 128>>>(h4, w5, h5);
    }

    yolo_head_kernel<<<dim3(BATCH, HEAD_OUT), 224>>>(h5, wh, pred);
    yolo_decode_kernel<<<BATCH, 224>>>(pred, boxes, cls, out);
    yolo_nms_kernel<<<dim3(NUM_CLS, BATCH), 224>>>(boxes, cls, out);
}